// round 7
// baseline (speedup 1.0000x reference)
#include <cuda_runtime.h>
#include <cuda_fp16.h>

// ---------------------------------------------------------------------------
// GAE-with-attributes. Outputs: x_hat[N,128] | e_hat[N,3] | z[N,64] | ge[500,64]
// CSR-gather GAT (fp16 h, fp32 scores/accum) + f32x2 GEMMs + fused decoder.
// CSR build runs on a forked stream, overlapped with the first GEMM.
// ---------------------------------------------------------------------------

#define MAXN 50048
#define MAXE 800001
#define NGRAPH 500
#define SCHUNK 2048
#define SBLOCKS ((MAXN + SCHUNK - 1) / SCHUNK)

__device__ __align__(16) __half2 g_h2[MAXN * 32];  // h in fp16, 32 half2 per row
__device__ __align__(16) float g_feat[MAXN * 64];
__device__ float g_ss[MAXN];
__device__ float g_sd[MAXN];
__device__ __align__(16) int g_deg[MAXN + 8];
__device__ int g_rowptr[MAXN + 1];
__device__ int g_cursor[MAXN];
__device__ int g_csrc[MAXE];
__device__ int g_s32[MAXE];
__device__ int g_d32[MAXE];
__device__ int g_bsum[SBLOCKS + 1];
__device__ float g_sums[NGRAPH * 64];
__device__ float g_cnt[NGRAPH + 12];
__device__ int g_mode;  // 1 = int64 indices on disk, 0 = int32

typedef unsigned long long ull;

__device__ __forceinline__ ull ffma2(ull a, ull b, ull c) {
    ull d;
    asm("fma.rn.f32x2 %0, %1, %2, %3;" : "=l"(d) : "l"(a), "l"(b), "l"(c));
    return d;
}
__device__ __forceinline__ ull pk2(float x, float y) {
    ull r;
    asm("mov.b64 %0, {%1,%2};" : "=l"(r) : "f"(x), "f"(y));
    return r;
}
__device__ __forceinline__ float2 up2(ull v) {
    float2 r;
    asm("mov.b64 {%0,%1}, %2;" : "=f"(r.x), "=f"(r.y) : "l"(v));
    return r;
}
__device__ __forceinline__ int eidx(const int* __restrict__ p, int i) {
    return g_mode ? p[2 * i] : p[i];
}
__device__ __forceinline__ float lrelu(float a) { return a > 0.f ? a : 0.2f * a; }

__global__ void k_detect(const int* __restrict__ ei) {
    int is64 = 1;
#pragma unroll
    for (int k = 0; k < 8; k++)
        if (ei[2 * k + 1] != 0) is64 = 0;
    g_mode = is64;
}

// ------------------------- CSR build (side stream) --------------------------
__global__ void k_initdeg(int n) {
    int i = blockIdx.x * blockDim.x + threadIdx.x;
    if (i < n + 8) g_deg[i] = 0;
    if (i < NGRAPH * 64) g_sums[i] = 0.f;
    if (i < NGRAPH) g_cnt[i] = 0.f;
}

__global__ void k_hist(const int* __restrict__ ei, int ne) {
    int e = blockIdx.x * blockDim.x + threadIdx.x;
    if (e >= ne) return;
    int s = eidx(ei, e);
    int d = eidx(ei, ne + e);
    g_s32[e] = s;
    g_d32[e] = d;
    atomicAdd(&g_deg[d], 1);
}

__global__ void k_scan1(int n) {
    __shared__ int ws[16];
    int b = blockIdx.x, tid = threadIdx.x;
    int i = b * SCHUNK + tid * 4;
    int4 v = *(const int4*)&g_deg[i];
    int s = v.x + v.y + v.z + v.w;
#pragma unroll
    for (int o = 16; o; o >>= 1) s += __shfl_xor_sync(0xffffffffu, s, o);
    if ((tid & 31) == 0) ws[tid >> 5] = s;
    __syncthreads();
    if (tid < 16) {
        int t = ws[tid];
#pragma unroll
        for (int o = 8; o; o >>= 1) t += __shfl_xor_sync(0xffffu, t, o);
        if (tid == 0) g_bsum[b] = t;
    }
}

__global__ void k_scan2(int nb) {
    int lane = threadIdx.x;
    int v = (lane < nb) ? g_bsum[lane] : 0;
    int x = v;
#pragma unroll
    for (int o = 1; o < 32; o <<= 1) {
        int t = __shfl_up_sync(0xffffffffu, x, o);
        if (lane >= o) x += t;
    }
    if (lane < nb) g_bsum[lane] = x - v;
}

__global__ void k_scan3(int n, int ne) {
    __shared__ int ws[16];
    int b = blockIdx.x, tid = threadIdx.x;
    int lane = tid & 31, wid = tid >> 5;
    int i = b * SCHUNK + tid * 4;
    int4 v = *(const int4*)&g_deg[i];
    int ts = v.x + v.y + v.z + v.w;
    int x = ts;
#pragma unroll
    for (int o = 1; o < 32; o <<= 1) {
        int t = __shfl_up_sync(0xffffffffu, x, o);
        if (lane >= o) x += t;
    }
    if (lane == 31) ws[wid] = x;
    __syncthreads();
    if (wid == 0 && lane < 16) {
        int y = ws[lane];
#pragma unroll
        for (int o = 1; o < 16; o <<= 1) {
            int t = __shfl_up_sync(0xffffu, y, o);
            if (lane >= o) y += t;
        }
        ws[lane] = y;
    }
    __syncthreads();
    int run = x - ts + (wid ? ws[wid - 1] : 0) + g_bsum[b];
    int e[4] = {v.x, v.y, v.z, v.w};
#pragma unroll
    for (int j = 0; j < 4; j++) {
        if (i + j < n) { g_rowptr[i + j] = run; g_cursor[i + j] = run; }
        run += e[j];
    }
    if (b == 0 && tid == 0) g_rowptr[n] = ne;
}

__global__ void k_scatter(int ne) {
    int e = blockIdx.x * blockDim.x + threadIdx.x;
    if (e >= ne) return;
    int pos = atomicAdd(&g_cursor[g_d32[e]], 1);
    g_csrc[pos] = g_s32[e];
}

// ------------------------- GAT transform GEMM -------------------------------
// column-pair f32x2: W loaded as ulonglong2 (zero packing movs for W side).
#define SRC_P 0
#define SRC_FEAT 1

template <int K, int SRC>
__global__ void k_gemm(const float* __restrict__ pin, const float* __restrict__ W,
                       const float* __restrict__ asrc, const float* __restrict__ adst, int n) {
    constexpr int F = 64;
    constexpr int KC = 64;
    __shared__ float sW[KC * F];
    __shared__ float sx[KC][64 + 4];
    const float* in = (SRC == 1) ? g_feat : pin;
    int tid = threadIdx.x;
    int cx = tid & 15, rx = tid >> 4;
    float avs[4], avd[4];
#pragma unroll
    for (int c = 0; c < 4; c++) { avs[c] = asrc[cx * 4 + c]; avd[c] = adst[cx * 4 + c]; }
    for (int base = blockIdx.x * 64; base < n; base += gridDim.x * 64) {
        ull accA[4], accB[4];  // accA[r]=(c0,c1), accB[r]=(c2,c3)
#pragma unroll
        for (int r = 0; r < 4; r++) { accA[r] = 0ull; accB[r] = 0ull; }
        for (int kc = 0; kc < K; kc += KC) {
            __syncthreads();
            for (int i = tid * 4; i < KC * F; i += 1024)
                *(float4*)&sW[i] = *(const float4*)&W[(size_t)(kc + i / F) * F + (i % F)];
            for (int t = tid; t < 64 * (KC / 4); t += 256) {
                int r = t / (KC / 4), kq = t % (KC / 4);
                int row = base + r;
                float4 v = (row < n) ? *(const float4*)&in[(size_t)row * K + kc + kq * 4]
                                     : make_float4(0.f, 0.f, 0.f, 0.f);
                sx[kq * 4 + 0][r] = v.x; sx[kq * 4 + 1][r] = v.y;
                sx[kq * 4 + 2][r] = v.z; sx[kq * 4 + 3][r] = v.w;
            }
            __syncthreads();
#pragma unroll 4
            for (int k = 0; k < KC; k++) {
                float4 xv = *(const float4*)&sx[k][rx * 4];
                ulonglong2 wv = *(const ulonglong2*)&sW[k * F + cx * 4];
                ull xd0 = pk2(xv.x, xv.x), xd1 = pk2(xv.y, xv.y);
                ull xd2 = pk2(xv.z, xv.z), xd3 = pk2(xv.w, xv.w);
                accA[0] = ffma2(wv.x, xd0, accA[0]); accB[0] = ffma2(wv.y, xd0, accB[0]);
                accA[1] = ffma2(wv.x, xd1, accA[1]); accB[1] = ffma2(wv.y, xd1, accB[1]);
                accA[2] = ffma2(wv.x, xd2, accA[2]); accB[2] = ffma2(wv.y, xd2, accB[2]);
                accA[3] = ffma2(wv.x, xd3, accA[3]); accB[3] = ffma2(wv.y, xd3, accB[3]);
            }
        }
        float vals[4][4];
#pragma unroll
        for (int r = 0; r < 4; r++) {
            float2 a = up2(accA[r]), b = up2(accB[r]);
            vals[r][0] = a.x; vals[r][1] = a.y; vals[r][2] = b.x; vals[r][3] = b.y;
        }
#pragma unroll
        for (int rp = 0; rp < 4; rp++) {
            float s = 0.f, d2 = 0.f;
#pragma unroll
            for (int c = 0; c < 4; c++) {
                s = fmaf(vals[rp][c], avs[c], s);
                d2 = fmaf(vals[rp][c], avd[c], d2);
            }
#pragma unroll
            for (int o = 8; o; o >>= 1) {
                s += __shfl_xor_sync(0xffffffffu, s, o);
                d2 += __shfl_xor_sync(0xffffffffu, d2, o);
            }
            int row = base + rx * 4 + rp;
            if (cx == 0 && row < n) { g_ss[row] = s; g_sd[row] = d2; }
        }
#pragma unroll
        for (int rp = 0; rp < 4; rp++) {
            int row = base + rx * 4 + rp;
            if (row < n) {
                __half2* hp = &g_h2[(size_t)row * 32 + cx * 2];
                hp[0] = __floats2half2_rn(vals[rp][0], vals[rp][1]);
                hp[1] = __floats2half2_rn(vals[rp][2], vals[rp][3]);
            }
        }
    }
}

// ------------------------- GAT aggregation ----------------------------------
// warp per dst; fp16 h rows (half traffic), fp32 scores + accumulation.
template <bool RELU>
__global__ void k_gather(const float* __restrict__ bias, int n) {
    int w = (blockIdx.x * blockDim.x + threadIdx.x) >> 5;
    int lane = threadIdx.x & 31;
    if (w >= n) return;
    int d = w;
    float sdd = g_sd[d];
    int p0 = g_rowptr[d], p1 = g_rowptr[d + 1];
    float wself = __expf(lrelu(g_ss[d] + sdd));
    float den = wself;
    float2 acc = __half22float2(g_h2[(size_t)d * 32 + lane]);
    acc.x *= wself; acc.y *= wself;
    int p = p0;
    for (; p + 4 <= p1; p += 4) {
        int s0 = g_csrc[p + 0];
        int s1 = g_csrc[p + 1];
        int s2 = g_csrc[p + 2];
        int s3 = g_csrc[p + 3];
        float t0 = g_ss[s0], t1 = g_ss[s1], t2 = g_ss[s2], t3 = g_ss[s3];
        float2 h0 = __half22float2(g_h2[(size_t)s0 * 32 + lane]);
        float2 h1 = __half22float2(g_h2[(size_t)s1 * 32 + lane]);
        float2 h2 = __half22float2(g_h2[(size_t)s2 * 32 + lane]);
        float2 h3 = __half22float2(g_h2[(size_t)s3 * 32 + lane]);
        float w0 = __expf(lrelu(t0 + sdd));
        float w1 = __expf(lrelu(t1 + sdd));
        float w2 = __expf(lrelu(t2 + sdd));
        float w3 = __expf(lrelu(t3 + sdd));
        den += (w0 + w1) + (w2 + w3);
        acc.x = fmaf(w0, h0.x, acc.x); acc.y = fmaf(w0, h0.y, acc.y);
        acc.x = fmaf(w1, h1.x, acc.x); acc.y = fmaf(w1, h1.y, acc.y);
        acc.x = fmaf(w2, h2.x, acc.x); acc.y = fmaf(w2, h2.y, acc.y);
        acc.x = fmaf(w3, h3.x, acc.x); acc.y = fmaf(w3, h3.y, acc.y);
    }
    for (; p < p1; p++) {
        int s0 = g_csrc[p];
        float w0 = __expf(lrelu(g_ss[s0] + sdd));
        float2 h0 = __half22float2(g_h2[(size_t)s0 * 32 + lane]);
        den += w0;
        acc.x = fmaf(w0, h0.x, acc.x); acc.y = fmaf(w0, h0.y, acc.y);
    }
    float inv = 1.f / (den + 1e-16f);
    float2 bb = *(const float2*)&bias[lane * 2];
    float2 o;
    o.x = acc.x * inv + bb.x;
    o.y = acc.y * inv + bb.y;
    if (RELU) { o.x = fmaxf(o.x, 0.f); o.y = fmaxf(o.y, 0.f); }
    *(float2*)&g_feat[(size_t)d * 64 + lane * 2] = o;
}

// ------------------------- fused decoder tail -------------------------------
#define TP 68

__device__ __forceinline__ void core64(const float* __restrict__ sIn,
                                       const float* __restrict__ sWc, int pitch,
                                       int rx, float vals[4][4], const float* __restrict__ b4) {
    ull accA[4], accB[4];
#pragma unroll
    for (int r = 0; r < 4; r++) { accA[r] = 0ull; accB[r] = 0ull; }
#pragma unroll 4
    for (int k = 0; k < 64; k++) {
        float4 xv = *(const float4*)&sIn[k * TP + rx * 4];
        ulonglong2 wv = *(const ulonglong2*)&sWc[k * pitch];
        ull xd0 = pk2(xv.x, xv.x), xd1 = pk2(xv.y, xv.y);
        ull xd2 = pk2(xv.z, xv.z), xd3 = pk2(xv.w, xv.w);
        accA[0] = ffma2(wv.x, xd0, accA[0]); accB[0] = ffma2(wv.y, xd0, accB[0]);
        accA[1] = ffma2(wv.x, xd1, accA[1]); accB[1] = ffma2(wv.y, xd1, accB[1]);
        accA[2] = ffma2(wv.x, xd2, accA[2]); accB[2] = ffma2(wv.y, xd2, accB[2]);
        accA[3] = ffma2(wv.x, xd3, accA[3]); accB[3] = ffma2(wv.y, xd3, accB[3]);
    }
#pragma unroll
    for (int r = 0; r < 4; r++) {
        float2 a = up2(accA[r]), b = up2(accB[r]);
        vals[r][0] = a.x + b4[0]; vals[r][1] = a.y + b4[1];
        vals[r][2] = b.x + b4[2]; vals[r][3] = b.y + b4[3];
    }
}

__device__ __forceinline__ void loadW(float* sW, const float* __restrict__ W, int cnt, int tid) {
    for (int i = tid * 4; i < cnt; i += 1024)
        *(float4*)&sW[i] = *(const float4*)&W[i];
}

__global__ void k_decoder(const float* __restrict__ linW, const float* __restrict__ linb,
                          const float* __restrict__ xmW1, const float* __restrict__ xmb1,
                          const float* __restrict__ xmW2, const float* __restrict__ xmb2,
                          const float* __restrict__ emW1, const float* __restrict__ emb1,
                          const float* __restrict__ emW2, const float* __restrict__ emb2,
                          const int* __restrict__ batch,
                          float* __restrict__ xhat, float* __restrict__ ehat,
                          float* __restrict__ z, int n) {
    extern __shared__ float smem[];
    float* sA = smem;
    float* sB = smem + 64 * TP;
    float* sW = smem + 2 * 64 * TP;
    int* sbatch = (int*)(sW + 8192);
    int tid = threadIdx.x;
    int cx = tid & 15, rx = tid >> 4;
    int base = blockIdx.x * 64;
    int nrows = min(64, n - base);

    for (int t = tid; t < 64 * 16; t += 256) {
        int r = t >> 4, kq = t & 15;
        int row = base + r;
        float4 v = (row < n) ? *(const float4*)&g_feat[(size_t)row * 64 + kq * 4]
                             : make_float4(0.f, 0.f, 0.f, 0.f);
        sA[(kq * 4 + 0) * TP + r] = v.x; sA[(kq * 4 + 1) * TP + r] = v.y;
        sA[(kq * 4 + 2) * TP + r] = v.z; sA[(kq * 4 + 3) * TP + r] = v.w;
    }
    loadW(sW, linW, 4096, tid);
    if (tid < 64) {
        int row = base + tid;
        sbatch[tid] = (row < n) ? (g_mode ? batch[2 * row] : batch[row]) : -1;
    }
    __syncthreads();

    {
        float b4[4];
        *(float4*)b4 = *(const float4*)&linb[cx * 4];
        float vals[4][4];
        core64(sA, sW + cx * 4, 64, rx, vals, b4);
#pragma unroll
        for (int rp = 0; rp < 4; rp++) {
            int r = rx * 4 + rp;
            int row = base + r;
            if (row < n)
                *(float4*)&z[(size_t)row * 64 + cx * 4] =
                    make_float4(vals[rp][0], vals[rp][1], vals[rp][2], vals[rp][3]);
#pragma unroll
            for (int c = 0; c < 4; c++) sB[(cx * 4 + c) * TP + r] = vals[rp][c];
        }
    }
    __syncthreads();

    {
        int col = tid & 63, q = tid >> 6;
        int r0 = q * 16, rend = min(r0 + 16, nrows);
        float accp = 0.f; float cnt = 0.f; int cur = -1;
        for (int r = r0; r < rend; r++) {
            int b = sbatch[r];
            if (b != cur) {
                if (cur >= 0) {
                    atomicAdd(&g_sums[cur * 64 + col], accp);
                    if (col == 0) atomicAdd(&g_cnt[cur], cnt);
                }
                cur = b; accp = 0.f; cnt = 0.f;
            }
            accp += sB[col * TP + r];
            cnt += 1.f;
        }
        if (cur >= 0) {
            atomicAdd(&g_sums[cur * 64 + col], accp);
            if (col == 0) atomicAdd(&g_cnt[cur], cnt);
        }
    }

    __syncthreads();
    loadW(sW, xmW1, 4096, tid);
    __syncthreads();
    {
        float b4[4];
        *(float4*)b4 = *(const float4*)&xmb1[cx * 4];
        float vals[4][4];
        core64(sB, sW + cx * 4, 64, rx, vals, b4);
        __syncthreads();
#pragma unroll
        for (int rp = 0; rp < 4; rp++) {
            int r = rx * 4 + rp;
#pragma unroll
            for (int c = 0; c < 4; c++) sA[(cx * 4 + c) * TP + r] = fmaxf(vals[rp][c], 0.f);
        }
    }
    __syncthreads();

    loadW(sW, xmW2, 8192, tid);
    __syncthreads();
#pragma unroll
    for (int half = 0; half < 2; half++) {
        int cb = cx * 4 + half * 64;
        float b4[4];
        *(float4*)b4 = *(const float4*)&xmb2[cb];
        float vals[4][4];
        core64(sA, sW + cb, 128, rx, vals, b4);
#pragma unroll
        for (int rp = 0; rp < 4; rp++) {
            int row = base + rx * 4 + rp;
            if (row < n)
                *(float4*)&xhat[(size_t)row * 128 + cb] =
                    make_float4(vals[rp][0], vals[rp][1], vals[rp][2], vals[rp][3]);
        }
    }

    __syncthreads();
    loadW(sW, emW1, 4096, tid);
    __syncthreads();
    {
        float b4[4];
        *(float4*)b4 = *(const float4*)&emb1[cx * 4];
        float vals[4][4];
        core64(sB, sW + cx * 4, 64, rx, vals, b4);
        __syncthreads();
#pragma unroll
        for (int rp = 0; rp < 4; rp++) {
            int r = rx * 4 + rp;
#pragma unroll
            for (int c = 0; c < 4; c++) sA[(cx * 4 + c) * TP + r] = fmaxf(vals[rp][c], 0.f);
        }
    }
    __syncthreads();

    loadW(sW, emW2, 192, tid);
    __syncthreads();
    if (tid < 192) {
        int r = tid & 63, c = tid >> 6;
        float a = emb2[c];
#pragma unroll 8
        for (int k = 0; k < 64; k++) a = fmaf(sA[k * TP + r], sW[k * 3 + c], a);
        int row = base + r;
        if (row < n) ehat[(size_t)row * 3 + c] = a;
    }
}

__global__ void k_ge(float* __restrict__ out) {
    int i = blockIdx.x * blockDim.x + threadIdx.x;
    if (i >= NGRAPH * 64) return;
    out[i] = g_sums[i] / fmaxf(g_cnt[i >> 6], 1.f);
}

extern "C" void kernel_launch(void* const* d_in, const int* in_sizes, int n_in,
                              void* d_out, int out_size) {
    const float* x     = (const float*)d_in[0];
    const int*   ei    = (const int*)d_in[1];
    const int*   batch = (const int*)d_in[2];
    const float* W1    = (const float*)d_in[4];
    const float* as1   = (const float*)d_in[5];
    const float* ad1   = (const float*)d_in[6];
    const float* b1    = (const float*)d_in[7];
    const float* W2    = (const float*)d_in[8];
    const float* as2   = (const float*)d_in[9];
    const float* ad2   = (const float*)d_in[10];
    const float* b2    = (const float*)d_in[11];
    const float* linW  = (const float*)d_in[12];
    const float* linb  = (const float*)d_in[13];
    const float* xmW1  = (const float*)d_in[14];
    const float* xmb1  = (const float*)d_in[15];
    const float* xmW2  = (const float*)d_in[16];
    const float* xmb2  = (const float*)d_in[17];
    const float* emW1  = (const float*)d_in[18];
    const float* emb1  = (const float*)d_in[19];
    const float* emW2  = (const float*)d_in[20];
    const float* emb2  = (const float*)d_in[21];

    int n  = in_sizes[0] / 128;  // 50000
    int ne = in_sizes[1] / 2;    // 800000

    float* out  = (float*)d_out;
    float* xhat = out;
    float* ehat = out + (size_t)n * 128;
    float* z    = ehat + (size_t)n * 3;
    float* ge   = z + (size_t)n * 64;

    int tiles = (n + 63) / 64;
    int gwarp = (n * 32 + 255) / 256;
    int nsb   = (n + SCHUNK - 1) / SCHUNK;

    static int inited = 0;
    static cudaStream_t s2;
    static cudaEvent_t eFork, eJoin;
    const int DEC_SMEM = (2 * 64 * TP + 8192 + 64) * 4;
    if (!inited) {
        cudaFuncSetAttribute(k_decoder, cudaFuncAttributeMaxDynamicSharedMemorySize, DEC_SMEM);
        cudaStreamCreateWithFlags(&s2, cudaStreamNonBlocking);
        cudaEventCreateWithFlags(&eFork, cudaEventDisableTiming);
        cudaEventCreateWithFlags(&eJoin, cudaEventDisableTiming);
        inited = 1;
    }

    k_detect<<<1, 1>>>(ei);

    // fork: CSR build + pool init on s2, GEMM1 on main stream
    cudaEventRecord(eFork, 0);
    cudaStreamWaitEvent(s2, eFork, 0);

    k_initdeg<<<(n + 8 + 255) / 256, 256, 0, s2>>>(n);
    k_hist<<<(ne + 255) / 256, 256, 0, s2>>>(ei, ne);
    k_scan1<<<nsb, 512, 0, s2>>>(n);
    k_scan2<<<1, 32, 0, s2>>>(nsb);
    k_scan3<<<nsb, 512, 0, s2>>>(n, ne);
    k_scatter<<<(ne + 255) / 256, 256, 0, s2>>>(ne);

    k_gemm<128, SRC_P><<<tiles, 256>>>(x, W1, as1, ad1, n);

    // join
    cudaEventRecord(eJoin, s2);
    cudaStreamWaitEvent(0, eJoin, 0);

    // ---- GAT layer 1 aggregation ----
    k_gather<true><<<gwarp, 256>>>(b1, n);

    // ---- GAT layer 2 ----
    k_gemm<64, SRC_FEAT><<<tiles, 256>>>(nullptr, W2, as2, ad2, n);
    k_gather<false><<<gwarp, 256>>>(b2, n);

    // ---- fused decoder tail ----
    k_decoder<<<tiles, 256, DEC_SMEM>>>(linW, linb, xmW1, xmb1, xmW2, xmb2,
                                        emW1, emb1, emW2, emb2, batch,
                                        xhat, ehat, z, n);
    k_ge<<<(NGRAPH * 64 + 255) / 256, 256>>>(ge);
}

// round 8
// speedup vs baseline: 1.0868x; 1.0868x over previous
#include <cuda_runtime.h>

// ---------------------------------------------------------------------------
// GAE-with-attributes. Outputs: x_hat[N,128] | e_hat[N,3] | z[N,64] | ge[500,64]
// CSR-gather GAT (half-warp edge-pair gather) + f32x2 GEMMs + fused decoder.
// CSR build runs on a forked stream, overlapped with the first GEMM.
// ---------------------------------------------------------------------------

#define MAXN 50048
#define MAXE 800001
#define NGRAPH 500
#define SCHUNK 2048
#define SBLOCKS ((MAXN + SCHUNK - 1) / SCHUNK)

__device__ __align__(16) float g_h[MAXN * 64];
__device__ __align__(16) float g_feat[MAXN * 64];
__device__ float g_ss[MAXN];
__device__ float g_sd[MAXN];
__device__ __align__(16) int g_deg[MAXN + 8];
__device__ int g_rowptr[MAXN + 1];
__device__ int g_cursor[MAXN];
__device__ int g_csrc[MAXE];
__device__ int g_s32[MAXE];
__device__ int g_d32[MAXE];
__device__ int g_bsum[SBLOCKS + 1];
__device__ float g_sums[NGRAPH * 64];
__device__ float g_cnt[NGRAPH + 12];
__device__ int g_mode;  // 1 = int64 indices on disk, 0 = int32

typedef unsigned long long ull;

__device__ __forceinline__ ull ffma2(ull a, ull b, ull c) {
    ull d;
    asm("fma.rn.f32x2 %0, %1, %2, %3;" : "=l"(d) : "l"(a), "l"(b), "l"(c));
    return d;
}
__device__ __forceinline__ ull pk2(float x, float y) {
    ull r;
    asm("mov.b64 %0, {%1,%2};" : "=l"(r) : "f"(x), "f"(y));
    return r;
}
__device__ __forceinline__ float2 up2(ull v) {
    float2 r;
    asm("mov.b64 {%0,%1}, %2;" : "=f"(r.x), "=f"(r.y) : "l"(v));
    return r;
}
__device__ __forceinline__ int eidx(const int* __restrict__ p, int i) {
    return g_mode ? p[2 * i] : p[i];
}
__device__ __forceinline__ float lrelu(float a) { return a > 0.f ? a : 0.2f * a; }

__global__ void k_detect(const int* __restrict__ ei) {
    int is64 = 1;
#pragma unroll
    for (int k = 0; k < 8; k++)
        if (ei[2 * k + 1] != 0) is64 = 0;
    g_mode = is64;
}

// ------------------------- CSR build (side stream) --------------------------
__global__ void k_initdeg(int n) {
    int i = blockIdx.x * blockDim.x + threadIdx.x;
    if (i < n + 8) g_deg[i] = 0;
    if (i < NGRAPH * 64) g_sums[i] = 0.f;
    if (i < NGRAPH) g_cnt[i] = 0.f;
}

__global__ void k_hist(const int* __restrict__ ei, int ne) {
    int e = blockIdx.x * blockDim.x + threadIdx.x;
    if (e >= ne) return;
    int s = eidx(ei, e);
    int d = eidx(ei, ne + e);
    g_s32[e] = s;
    g_d32[e] = d;
    atomicAdd(&g_deg[d], 1);
}

__global__ void k_scan1(int n) {
    __shared__ int ws[16];
    int b = blockIdx.x, tid = threadIdx.x;
    int i = b * SCHUNK + tid * 4;
    int4 v = *(const int4*)&g_deg[i];
    int s = v.x + v.y + v.z + v.w;
#pragma unroll
    for (int o = 16; o; o >>= 1) s += __shfl_xor_sync(0xffffffffu, s, o);
    if ((tid & 31) == 0) ws[tid >> 5] = s;
    __syncthreads();
    if (tid < 16) {
        int t = ws[tid];
#pragma unroll
        for (int o = 8; o; o >>= 1) t += __shfl_xor_sync(0xffffu, t, o);
        if (tid == 0) g_bsum[b] = t;
    }
}

__global__ void k_scan2(int nb) {
    int lane = threadIdx.x;
    int v = (lane < nb) ? g_bsum[lane] : 0;
    int x = v;
#pragma unroll
    for (int o = 1; o < 32; o <<= 1) {
        int t = __shfl_up_sync(0xffffffffu, x, o);
        if (lane >= o) x += t;
    }
    if (lane < nb) g_bsum[lane] = x - v;
}

__global__ void k_scan3(int n, int ne) {
    __shared__ int ws[16];
    int b = blockIdx.x, tid = threadIdx.x;
    int lane = tid & 31, wid = tid >> 5;
    int i = b * SCHUNK + tid * 4;
    int4 v = *(const int4*)&g_deg[i];
    int ts = v.x + v.y + v.z + v.w;
    int x = ts;
#pragma unroll
    for (int o = 1; o < 32; o <<= 1) {
        int t = __shfl_up_sync(0xffffffffu, x, o);
        if (lane >= o) x += t;
    }
    if (lane == 31) ws[wid] = x;
    __syncthreads();
    if (wid == 0 && lane < 16) {
        int y = ws[lane];
#pragma unroll
        for (int o = 1; o < 16; o <<= 1) {
            int t = __shfl_up_sync(0xffffu, y, o);
            if (lane >= o) y += t;
        }
        ws[lane] = y;
    }
    __syncthreads();
    int run = x - ts + (wid ? ws[wid - 1] : 0) + g_bsum[b];
    int e[4] = {v.x, v.y, v.z, v.w};
#pragma unroll
    for (int j = 0; j < 4; j++) {
        if (i + j < n) { g_rowptr[i + j] = run; g_cursor[i + j] = run; }
        run += e[j];
    }
    if (b == 0 && tid == 0) g_rowptr[n] = ne;
}

__global__ void k_scatter(int ne) {
    int e = blockIdx.x * blockDim.x + threadIdx.x;
    if (e >= ne) return;
    int pos = atomicAdd(&g_cursor[g_d32[e]], 1);
    g_csrc[pos] = g_s32[e];
}

// ------------------------- GAT transform GEMM (round-6 proven form) ---------
#define SRC_P 0
#define SRC_FEAT 1

template <int K, int SRC>
__global__ void k_gemm(const float* __restrict__ pin, const float* __restrict__ W,
                       const float* __restrict__ asrc, const float* __restrict__ adst, int n) {
    constexpr int F = 64, CP = 4;
    constexpr int KC = 64;
    __shared__ float sW[KC * F];
    __shared__ float sx[KC][64 + 4];
    const float* in = (SRC == 1) ? g_feat : pin;
    int tid = threadIdx.x;
    int cx = tid & 15, rx = tid >> 4;
    float avs[CP], avd[CP];
#pragma unroll
    for (int c = 0; c < CP; c++) { avs[c] = asrc[cx * CP + c]; avd[c] = adst[cx * CP + c]; }
    for (int base = blockIdx.x * 64; base < n; base += gridDim.x * 64) {
        ull acc0[CP], acc1[CP];
#pragma unroll
        for (int c = 0; c < CP; c++) { acc0[c] = 0ull; acc1[c] = 0ull; }
        for (int kc = 0; kc < K; kc += KC) {
            __syncthreads();
            for (int i = tid * 4; i < KC * F; i += 1024)
                *(float4*)&sW[i] = *(const float4*)&W[(size_t)(kc + i / F) * F + (i % F)];
            for (int t = tid; t < 64 * (KC / 4); t += 256) {
                int r = t / (KC / 4), kq = t % (KC / 4);
                int row = base + r;
                float4 v = (row < n) ? *(const float4*)&in[(size_t)row * K + kc + kq * 4]
                                     : make_float4(0.f, 0.f, 0.f, 0.f);
                sx[kq * 4 + 0][r] = v.x; sx[kq * 4 + 1][r] = v.y;
                sx[kq * 4 + 2][r] = v.z; sx[kq * 4 + 3][r] = v.w;
            }
            __syncthreads();
#pragma unroll 4
            for (int k = 0; k < KC; k++) {
                float4 xv = *(const float4*)&sx[k][rx * 4];
                ull p0 = pk2(xv.x, xv.y), p1 = pk2(xv.z, xv.w);
#pragma unroll
                for (int c = 0; c < CP; c++) {
                    float w = sW[k * F + cx * CP + c];
                    ull wd = pk2(w, w);
                    acc0[c] = ffma2(p0, wd, acc0[c]);
                    acc1[c] = ffma2(p1, wd, acc1[c]);
                }
            }
        }
        float vals[4][CP];
#pragma unroll
        for (int c = 0; c < CP; c++) {
            float2 lo = up2(acc0[c]), hi = up2(acc1[c]);
            vals[0][c] = lo.x; vals[1][c] = lo.y; vals[2][c] = hi.x; vals[3][c] = hi.y;
        }
#pragma unroll
        for (int rp = 0; rp < 4; rp++) {
            float s = 0.f, d2 = 0.f;
#pragma unroll
            for (int c = 0; c < CP; c++) {
                s = fmaf(vals[rp][c], avs[c], s);
                d2 = fmaf(vals[rp][c], avd[c], d2);
            }
#pragma unroll
            for (int o = 8; o; o >>= 1) {
                s += __shfl_xor_sync(0xffffffffu, s, o);
                d2 += __shfl_xor_sync(0xffffffffu, d2, o);
            }
            int row = base + rx * 4 + rp;
            if (cx == 0 && row < n) { g_ss[row] = s; g_sd[row] = d2; }
        }
#pragma unroll
        for (int rp = 0; rp < 4; rp++) {
            int row = base + rx * 4 + rp;
            if (row < n)
                *(float4*)&g_h[(size_t)row * 64 + cx * CP] =
                    make_float4(vals[rp][0], vals[rp][1], vals[rp][2], vals[rp][3]);
        }
    }
}

// ------------------------- GAT aggregation ----------------------------------
// warp per dst node; half-warp edge pairing: lanes 0-15 take edge p, lanes
// 16-31 take edge p+1; each lane covers 4 channels. Each csrc/ss/h LDG
// instruction serves TWO edges -> 1.5 LDG/edge instead of 3 (LSU-issue bound).
template <bool RELU>
__global__ void k_gather(const float* __restrict__ bias, int n) {
    int w = (blockIdx.x * blockDim.x + threadIdx.x) >> 5;
    int lane = threadIdx.x & 31;
    if (w >= n) return;
    int d = w;
    int half = lane >> 4, q = lane & 15;
    float sdd = g_sd[d];
    int p0 = g_rowptr[d], p1 = g_rowptr[d + 1];
    // self loop counted in half 0 only
    float wself = (half == 0) ? __expf(lrelu(g_ss[d] + sdd)) : 0.f;
    float4 hd = *(const float4*)&g_h[(size_t)d * 64 + q * 4];
    float den = wself;
    float ax = wself * hd.x, ay = wself * hd.y, az = wself * hd.z, aw = wself * hd.w;
#pragma unroll 2
    for (int p = p0; p < p1; p += 2) {
        int idx = p + half;
        int ok = idx < p1;
        int s = g_csrc[ok ? idx : p];          // 1 LDG, 2 broadcast groups
        float t = g_ss[s];                     // 1 LDG, 2 addresses
        float4 hv = *(const float4*)&g_h[(size_t)s * 64 + q * 4];  // 1 LDG.128
        float wgt = ok ? __expf(lrelu(t + sdd)) : 0.f;
        den += wgt;
        ax = fmaf(wgt, hv.x, ax); ay = fmaf(wgt, hv.y, ay);
        az = fmaf(wgt, hv.z, az); aw = fmaf(wgt, hv.w, aw);
    }
    // combine the two halves (channels identical across halves)
    den += __shfl_xor_sync(0xffffffffu, den, 16);
    ax += __shfl_xor_sync(0xffffffffu, ax, 16);
    ay += __shfl_xor_sync(0xffffffffu, ay, 16);
    az += __shfl_xor_sync(0xffffffffu, az, 16);
    aw += __shfl_xor_sync(0xffffffffu, aw, 16);
    if (half == 0) {
        float inv = 1.f / (den + 1e-16f);
        float4 bb = *(const float4*)&bias[q * 4];
        float4 o;
        o.x = ax * inv + bb.x; o.y = ay * inv + bb.y;
        o.z = az * inv + bb.z; o.w = aw * inv + bb.w;
        if (RELU) {
            o.x = fmaxf(o.x, 0.f); o.y = fmaxf(o.y, 0.f);
            o.z = fmaxf(o.z, 0.f); o.w = fmaxf(o.w, 0.f);
        }
        *(float4*)&g_feat[(size_t)d * 64 + q * 4] = o;
    }
}

// ------------------------- fused decoder tail -------------------------------
#define TP 68

__device__ __forceinline__ void core64(const float* __restrict__ sIn,
                                       const float* __restrict__ sWc, int pitch,
                                       int rx, float vals[4][4], const float* __restrict__ b4) {
    ull a0[4], a1[4];
#pragma unroll
    for (int c = 0; c < 4; c++) { a0[c] = 0ull; a1[c] = 0ull; }
#pragma unroll 4
    for (int k = 0; k < 64; k++) {
        float4 xv = *(const float4*)&sIn[k * TP + rx * 4];
        ull p0 = pk2(xv.x, xv.y), p1 = pk2(xv.z, xv.w);
        float4 wv = *(const float4*)&sWc[k * pitch];
        ull w0 = pk2(wv.x, wv.x), w1 = pk2(wv.y, wv.y);
        ull w2 = pk2(wv.z, wv.z), w3 = pk2(wv.w, wv.w);
        a0[0] = ffma2(p0, w0, a0[0]); a1[0] = ffma2(p1, w0, a1[0]);
        a0[1] = ffma2(p0, w1, a0[1]); a1[1] = ffma2(p1, w1, a1[1]);
        a0[2] = ffma2(p0, w2, a0[2]); a1[2] = ffma2(p1, w2, a1[2]);
        a0[3] = ffma2(p0, w3, a0[3]); a1[3] = ffma2(p1, w3, a1[3]);
    }
#pragma unroll
    for (int c = 0; c < 4; c++) {
        float2 lo = up2(a0[c]), hi = up2(a1[c]);
        vals[0][c] = lo.x + b4[c]; vals[1][c] = lo.y + b4[c];
        vals[2][c] = hi.x + b4[c]; vals[3][c] = hi.y + b4[c];
    }
}

__device__ __forceinline__ void loadW(float* sW, const float* __restrict__ W, int cnt, int tid) {
    for (int i = tid * 4; i < cnt; i += 1024)
        *(float4*)&sW[i] = *(const float4*)&W[i];
}

__global__ void k_decoder(const float* __restrict__ linW, const float* __restrict__ linb,
                          const float* __restrict__ xmW1, const float* __restrict__ xmb1,
                          const float* __restrict__ xmW2, const float* __restrict__ xmb2,
                          const float* __restrict__ emW1, const float* __restrict__ emb1,
                          const float* __restrict__ emW2, const float* __restrict__ emb2,
                          const int* __restrict__ batch,
                          float* __restrict__ xhat, float* __restrict__ ehat,
                          float* __restrict__ z, int n) {
    extern __shared__ float smem[];
    float* sA = smem;
    float* sB = smem + 64 * TP;
    float* sW = smem + 2 * 64 * TP;
    int* sbatch = (int*)(sW + 8192);
    int tid = threadIdx.x;
    int cx = tid & 15, rx = tid >> 4;
    int base = blockIdx.x * 64;
    int nrows = min(64, n - base);

    for (int t = tid; t < 64 * 16; t += 256) {
        int r = t >> 4, kq = t & 15;
        int row = base + r;
        float4 v = (row < n) ? *(const float4*)&g_feat[(size_t)row * 64 + kq * 4]
                             : make_float4(0.f, 0.f, 0.f, 0.f);
        sA[(kq * 4 + 0) * TP + r] = v.x; sA[(kq * 4 + 1) * TP + r] = v.y;
        sA[(kq * 4 + 2) * TP + r] = v.z; sA[(kq * 4 + 3) * TP + r] = v.w;
    }
    loadW(sW, linW, 4096, tid);
    if (tid < 64) {
        int row = base + tid;
        sbatch[tid] = (row < n) ? (g_mode ? batch[2 * row] : batch[row]) : -1;
    }
    __syncthreads();

    {
        float b4[4];
        *(float4*)b4 = *(const float4*)&linb[cx * 4];
        float vals[4][4];
        core64(sA, sW + cx * 4, 64, rx, vals, b4);
#pragma unroll
        for (int rp = 0; rp < 4; rp++) {
            int r = rx * 4 + rp;
            int row = base + r;
            if (row < n)
                *(float4*)&z[(size_t)row * 64 + cx * 4] =
                    make_float4(vals[rp][0], vals[rp][1], vals[rp][2], vals[rp][3]);
#pragma unroll
            for (int c = 0; c < 4; c++) sB[(cx * 4 + c) * TP + r] = vals[rp][c];
        }
    }
    __syncthreads();

    {
        int col = tid & 63, q = tid >> 6;
        int r0 = q * 16, rend = min(r0 + 16, nrows);
        float accp = 0.f; float cnt = 0.f; int cur = -1;
        for (int r = r0; r < rend; r++) {
            int b = sbatch[r];
            if (b != cur) {
                if (cur >= 0) {
                    atomicAdd(&g_sums[cur * 64 + col], accp);
                    if (col == 0) atomicAdd(&g_cnt[cur], cnt);
                }
                cur = b; accp = 0.f; cnt = 0.f;
            }
            accp += sB[col * TP + r];
            cnt += 1.f;
        }
        if (cur >= 0) {
            atomicAdd(&g_sums[cur * 64 + col], accp);
            if (col == 0) atomicAdd(&g_cnt[cur], cnt);
        }
    }

    __syncthreads();
    loadW(sW, xmW1, 4096, tid);
    __syncthreads();
    {
        float b4[4];
        *(float4*)b4 = *(const float4*)&xmb1[cx * 4];
        float vals[4][4];
        core64(sB, sW + cx * 4, 64, rx, vals, b4);
        __syncthreads();
#pragma unroll
        for (int rp = 0; rp < 4; rp++) {
            int r = rx * 4 + rp;
#pragma unroll
            for (int c = 0; c < 4; c++) sA[(cx * 4 + c) * TP + r] = fmaxf(vals[rp][c], 0.f);
        }
    }
    __syncthreads();

    loadW(sW, xmW2, 8192, tid);
    __syncthreads();
#pragma unroll
    for (int half = 0; half < 2; half++) {
        int cb = cx * 4 + half * 64;
        float b4[4];
        *(float4*)b4 = *(const float4*)&xmb2[cb];
        float vals[4][4];
        core64(sA, sW + cb, 128, rx, vals, b4);
#pragma unroll
        for (int rp = 0; rp < 4; rp++) {
            int row = base + rx * 4 + rp;
            if (row < n)
                *(float4*)&xhat[(size_t)row * 128 + cb] =
                    make_float4(vals[rp][0], vals[rp][1], vals[rp][2], vals[rp][3]);
        }
    }

    __syncthreads();
    loadW(sW, emW1, 4096, tid);
    __syncthreads();
    {
        float b4[4];
        *(float4*)b4 = *(const float4*)&emb1[cx * 4];
        float vals[4][4];
        core64(sB, sW + cx * 4, 64, rx, vals, b4);
        __syncthreads();
#pragma unroll
        for (int rp = 0; rp < 4; rp++) {
            int r = rx * 4 + rp;
#pragma unroll
            for (int c = 0; c < 4; c++) sA[(cx * 4 + c) * TP + r] = fmaxf(vals[rp][c], 0.f);
        }
    }
    __syncthreads();

    loadW(sW, emW2, 192, tid);
    __syncthreads();
    if (tid < 192) {
        int r = tid & 63, c = tid >> 6;
        float a = emb2[c];
#pragma unroll 8
        for (int k = 0; k < 64; k++) a = fmaf(sA[k * TP + r], sW[k * 3 + c], a);
        int row = base + r;
        if (row < n) ehat[(size_t)row * 3 + c] = a;
    }
}

__global__ void k_ge(float* __restrict__ out) {
    int i = blockIdx.x * blockDim.x + threadIdx.x;
    if (i >= NGRAPH * 64) return;
    out[i] = g_sums[i] / fmaxf(g_cnt[i >> 6], 1.f);
}

extern "C" void kernel_launch(void* const* d_in, const int* in_sizes, int n_in,
                              void* d_out, int out_size) {
    const float* x     = (const float*)d_in[0];
    const int*   ei    = (const int*)d_in[1];
    const int*   batch = (const int*)d_in[2];
    const float* W1    = (const float*)d_in[4];
    const float* as1   = (const float*)d_in[5];
    const float* ad1   = (const float*)d_in[6];
    const float* b1    = (const float*)d_in[7];
    const float* W2    = (const float*)d_in[8];
    const float* as2   = (const float*)d_in[9];
    const float* ad2   = (const float*)d_in[10];
    const float* b2    = (const float*)d_in[11];
    const float* linW  = (const float*)d_in[12];
    const float* linb  = (const float*)d_in[13];
    const float* xmW1  = (const float*)d_in[14];
    const float* xmb1  = (const float*)d_in[15];
    const float* xmW2  = (const float*)d_in[16];
    const float* xmb2  = (const float*)d_in[17];
    const float* emW1  = (const float*)d_in[18];
    const float* emb1  = (const float*)d_in[19];
    const float* emW2  = (const float*)d_in[20];
    const float* emb2  = (const float*)d_in[21];

    int n  = in_sizes[0] / 128;  // 50000
    int ne = in_sizes[1] / 2;    // 800000

    float* out  = (float*)d_out;
    float* xhat = out;
    float* ehat = out + (size_t)n * 128;
    float* z    = ehat + (size_t)n * 3;
    float* ge   = z + (size_t)n * 64;

    int tiles = (n + 63) / 64;
    int gwarp = (n * 32 + 255) / 256;
    int nsb   = (n + SCHUNK - 1) / SCHUNK;

    static int inited = 0;
    static cudaStream_t s2;
    static cudaEvent_t eFork, eJoin;
    const int DEC_SMEM = (2 * 64 * TP + 8192 + 64) * 4;
    if (!inited) {
        cudaFuncSetAttribute(k_decoder, cudaFuncAttributeMaxDynamicSharedMemorySize, DEC_SMEM);
        cudaStreamCreateWithFlags(&s2, cudaStreamNonBlocking);
        cudaEventCreateWithFlags(&eFork, cudaEventDisableTiming);
        cudaEventCreateWithFlags(&eJoin, cudaEventDisableTiming);
        inited = 1;
    }

    k_detect<<<1, 1>>>(ei);

    // fork: CSR build + pool init on s2, GEMM1 on main stream
    cudaEventRecord(eFork, 0);
    cudaStreamWaitEvent(s2, eFork, 0);

    k_initdeg<<<(n + 8 + 255) / 256, 256, 0, s2>>>(n);
    k_hist<<<(ne + 255) / 256, 256, 0, s2>>>(ei, ne);
    k_scan1<<<nsb, 512, 0, s2>>>(n);
    k_scan2<<<1, 32, 0, s2>>>(nsb);
    k_scan3<<<nsb, 512, 0, s2>>>(n, ne);
    k_scatter<<<(ne + 255) / 256, 256, 0, s2>>>(ne);

    k_gemm<128, SRC_P><<<tiles, 256>>>(x, W1, as1, ad1, n);

    // join
    cudaEventRecord(eJoin, s2);
    cudaStreamWaitEvent(0, eJoin, 0);

    // ---- GAT layer 1 aggregation ----
    k_gather<true><<<gwarp, 256>>>(b1, n);

    // ---- GAT layer 2 ----
    k_gemm<64, SRC_FEAT><<<tiles, 256>>>(nullptr, W2, as2, ad2, n);
    k_gather<false><<<gwarp, 256>>>(b2, n);

    // ---- fused decoder tail ----
    k_decoder<<<tiles, 256, DEC_SMEM>>>(linW, linb, xmW1, xmb1, xmW2, xmb2,
                                        emW1, emb1, emW2, emb2, batch,
                                        xhat, ehat, z, n);
    k_ge<<<(NGRAPH * 64 + 255) / 256, 256>>>(ge);
}